// round 9
// baseline (speedup 1.0000x reference)
#include <cuda_runtime.h>
#include <cuda_fp16.h>
#include <cstdint>

#define NTOK 65536
#define D_IN 768
#define HID  512
#define CBD  256
#define CBK  512

// ---------------- scratch (device globals; no allocations) ----------------
__device__ __half g_xh[(size_t)NTOK * D_IN];
__device__ __half g_xl[(size_t)NTOK * D_IN];
__device__ __half g_hH[(size_t)NTOK * HID];
__device__ __half g_hL[(size_t)NTOK * HID];
__device__ __half g_zH[(size_t)NTOK * CBD];
__device__ __half g_zL[(size_t)NTOK * CBD];
__device__ float2 g_part[(size_t)NTOK * 4];   // per-128-code-block (val, idx)
__device__ __half g_W1TH[HID * D_IN];
__device__ __half g_W1TL[HID * D_IN];
__device__ __half g_W2TH[CBD * HID];
__device__ __half g_W2TL[CBD * HID];
__device__ __half g_cbH[CBK * CBD];
__device__ __half g_cbL[CBK * CBD];
__device__ float  g_T1[512 * 512];
__device__ float  g_R[512 * 768];
__device__ float  g_csq[CBK];
__device__ double g_commit;

// ---------------- helpers --------------------------------------------------
__device__ __forceinline__ void split_h(float v, __half& h, __half& l) {
    h = __float2half_rn(v);
    l = __float2half_rn(v - __half2float(h));
}
__device__ __forceinline__ void cp16(uint32_t saddr, const void* g) {
    asm volatile("cp.async.cg.shared.global [%0], [%1], 16;" :: "r"(saddr), "l"(g));
}
#define CP_COMMIT() asm volatile("cp.async.commit_group;" ::: "memory")
#define CP_WAIT2()  asm volatile("cp.async.wait_group 2;" ::: "memory")

#define LDSM4(r0, r1, r2, r3, addr) \
    asm volatile("ldmatrix.sync.aligned.m8n8.x4.shared.b16 {%0,%1,%2,%3}, [%4];" \
        : "=r"(r0), "=r"(r1), "=r"(r2), "=r"(r3) : "r"(addr))

#define MMA16(cc, aa, bb) \
    asm volatile("mma.sync.aligned.m16n8k16.row.col.f32.f16.f16.f32 " \
        "{%0,%1,%2,%3}, {%4,%5,%6,%7}, {%8,%9}, {%0,%1,%2,%3};" \
        : "+f"((cc)[0]), "+f"((cc)[1]), "+f"((cc)[2]), "+f"((cc)[3]) \
        : "r"((aa)[0]), "r"((aa)[1]), "r"((aa)[2]), "r"((aa)[3]), \
          "r"((bb)[0]), "r"((bb)[1]))

// =================== fp16 3x-split HMMA GEMM ===============================
// C[N, M] = op((Ah+Al)[N,K] @ (Bh+Bl)^T + bias); planes are __half [.,K] rowmaj.
// CTA tile 128x128, 4 warps each 64x64, K-tile 16, 4-stage cp.async pipeline.
// Stage (bytes): Ah@0, Al@6144, Bh@12288, Bl@18432; row stride 48B (24 halves).
// ARGMIN: no C store; per-row argmin of (csq[col] - 2*acc) over the 128 cols,
// partials to part[token*4 + blockIdx.x].
#define STAGE_B  24576
#define HSMEM    (4 * STAGE_B)

template<bool RELU, bool HASBIAS, bool OSPLIT, bool ARGMIN>
__global__ void __launch_bounds__(128, 2) hmma_gemm(
    const __half* __restrict__ Ah, const __half* __restrict__ Al,
    const __half* __restrict__ Bh, const __half* __restrict__ Bl,
    const float* __restrict__ bias,
    float* __restrict__ C, __half* __restrict__ Ch, __half* __restrict__ Cl,
    float2* __restrict__ part, int K, int M)
{
    extern __shared__ char hsm[];
    __shared__ float2 red[2][64][2];
    uint32_t sbase;
    asm("{ .reg .u64 t; cvta.to.shared.u64 t, %1; cvt.u32.u64 %0, t; }"
        : "=r"(sbase) : "l"(hsm));

    const int tid  = threadIdx.x;
    const int lane = tid & 31;
    const int wid  = tid >> 5;
    const int wm   = wid & 1;           // row band (2 x 64)
    const int wn   = wid >> 1;          // col band (2 x 64)
    const int group = lane >> 2;
    const int tig   = lane & 3;
    const int brow = blockIdx.y << 7;
    const int bcol = blockIdx.x << 7;

    // loader: thread -> rows (tid>>1, +64), 16B chunk (tid&1), each plane
    const int lrow = tid >> 1;
    const int lchk = tid & 1;
    const uint32_t soff = sbase + (uint32_t)(lrow * 48 + lchk * 16);
    const __half* gAh = Ah + (size_t)(brow + lrow) * K + lchk * 8;
    const __half* gAl = Al + (size_t)(brow + lrow) * K + lchk * 8;
    const __half* gBh = Bh + (size_t)(bcol + lrow) * K + lchk * 8;
    const __half* gBl = Bl + (size_t)(bcol + lrow) * K + lchk * 8;

    // ldmatrix lane offsets (bytes)
    const uint32_t aoff = (uint32_t)(((lane & 15) * 24 + (lane >> 4) * 8) * 2);
    const uint32_t boff = (uint32_t)((((lane & 7) + ((lane >> 4) << 3)) * 24 +
                                      ((lane >> 3) & 1) * 8) * 2);

    float c[4][8][4];
#pragma unroll
    for (int i = 0; i < 4; i++)
#pragma unroll
        for (int j = 0; j < 8; j++)
#pragma unroll
            for (int k = 0; k < 4; k++) c[i][j][k] = 0.f;

    const int KT = K >> 4;
    auto issue = [&](int kt) {
        const uint32_t sb = soff + (uint32_t)(kt & 3) * STAGE_B;
        const size_t go = (size_t)kt << 4;
        const size_t g1 = go + (size_t)64 * K;
        cp16(sb,                gAh + go);  cp16(sb + 3072,         gAh + g1);
        cp16(sb + 6144,         gAl + go);  cp16(sb + 6144 + 3072,  gAl + g1);
        cp16(sb + 12288,        gBh + go);  cp16(sb + 12288 + 3072, gBh + g1);
        cp16(sb + 18432,        gBl + go);  cp16(sb + 18432 + 3072, gBl + g1);
    };

    issue(0); CP_COMMIT();
    issue(1); CP_COMMIT();
    issue(2); CP_COMMIT();

    for (int kt = 0; kt < KT; kt++) {
        CP_WAIT2();
        __syncthreads();
        if (kt + 3 < KT) issue(kt + 3);
        CP_COMMIT();

        const uint32_t st = sbase + (uint32_t)(kt & 3) * STAGE_B;

        // B fragments: 8 nf (64 cols), hi and lo planes
        uint32_t bh[8][2], bl[8][2];
        {
            const uint32_t b0 = st + 12288 + (uint32_t)((wn << 6) * 48) + boff;
#pragma unroll
            for (int q = 0; q < 4; q++) {
                LDSM4(bh[2 * q][0], bh[2 * q][1], bh[2 * q + 1][0], bh[2 * q + 1][1],
                      b0 + q * 768);
                LDSM4(bl[2 * q][0], bl[2 * q][1], bl[2 * q + 1][0], bl[2 * q + 1][1],
                      b0 + q * 768 + 6144);
            }
        }
#pragma unroll
        for (int mf = 0; mf < 4; mf++) {
            const uint32_t a0 = st + (uint32_t)(((wm << 6) + (mf << 4)) * 48) + aoff;
            uint32_t ah[4], al[4];
            LDSM4(ah[0], ah[1], ah[2], ah[3], a0);
            LDSM4(al[0], al[1], al[2], al[3], a0 + 6144);
#pragma unroll
            for (int nf = 0; nf < 8; nf++) MMA16(c[mf][nf], ah, bh[nf]);
#pragma unroll
            for (int nf = 0; nf < 8; nf++) MMA16(c[mf][nf], al, bh[nf]);
#pragma unroll
            for (int nf = 0; nf < 8; nf++) MMA16(c[mf][nf], ah, bl[nf]);
        }
    }

    if (ARGMIN) {
        // rows: (wm<<6)+(mf<<4)+group (+8). local cols: (wn<<6)+(nf<<3)+(tig<<1)+{0,1}
#pragma unroll
        for (int mf = 0; mf < 4; mf++) {
#pragma unroll
            for (int sub = 0; sub < 2; sub++) {
                float bv = 3.4e38f;
                int   bi = 0;
#pragma unroll
                for (int nf = 0; nf < 8; nf++) {
                    const int col = (wn << 6) + (nf << 3) + (tig << 1);
                    float d0 = __ldg(&g_csq[bcol + col])     - 2.f * c[mf][nf][sub * 2];
                    float d1 = __ldg(&g_csq[bcol + col + 1]) - 2.f * c[mf][nf][sub * 2 + 1];
                    if (d0 < bv || (d0 == bv && col < bi))     { bv = d0; bi = col; }
                    if (d1 < bv || (d1 == bv && col + 1 < bi)) { bv = d1; bi = col + 1; }
                }
#pragma unroll
                for (int off = 1; off < 4; off <<= 1) {
                    float ov = __shfl_xor_sync(0xffffffffu, bv, off);
                    int   oi = __shfl_xor_sync(0xffffffffu, bi, off);
                    if (ov < bv || (ov == bv && oi < bi)) { bv = ov; bi = oi; }
                }
                if (tig == 0)
                    red[wm][(mf << 4) + group + sub * 8][wn] =
                        make_float2(bv, __int_as_float(bi));
            }
        }
        __syncthreads();
        {
            const int wmb = tid >> 6, rl = tid & 63;
            float bv = 3.4e38f;
            int   bi = 0;
#pragma unroll
            for (int w = 0; w < 2; w++) {
                float2 e = red[wmb][rl][w];
                int ei = __float_as_int(e.y);
                if (e.x < bv || (e.x == bv && ei < bi)) { bv = e.x; bi = ei; }
            }
            const int token = brow + (wmb << 6) + rl;
            part[(size_t)token * 4 + blockIdx.x] = make_float2(bv, (float)(bcol + bi));
        }
        return;
    }

    // normal epilogue
#pragma unroll
    for (int mf = 0; mf < 4; mf++) {
#pragma unroll
        for (int nf = 0; nf < 8; nf++) {
            const int row = brow + (wm << 6) + (mf << 4) + group;
            const int col = bcol + (wn << 6) + (nf << 3) + (tig << 1);
            float bx = 0.f, by = 0.f;
            if (HASBIAS) { bx = __ldg(bias + col); by = __ldg(bias + col + 1); }
            float2 o0, o1;
            o0.x = c[mf][nf][0] + bx;  o0.y = c[mf][nf][1] + by;
            o1.x = c[mf][nf][2] + bx;  o1.y = c[mf][nf][3] + by;
            if (RELU) {
                o0.x = fmaxf(o0.x, 0.f); o0.y = fmaxf(o0.y, 0.f);
                o1.x = fmaxf(o1.x, 0.f); o1.y = fmaxf(o1.y, 0.f);
            }
            if (OSPLIT) {
                __half hx, lx, hy, ly;
                split_h(o0.x, hx, lx); split_h(o0.y, hy, ly);
                *(__half2*)(Ch + (size_t)row * M + col) = __halves2half2(hx, hy);
                *(__half2*)(Cl + (size_t)row * M + col) = __halves2half2(lx, ly);
                split_h(o1.x, hx, lx); split_h(o1.y, hy, ly);
                *(__half2*)(Ch + (size_t)(row + 8) * M + col) = __halves2half2(hx, hy);
                *(__half2*)(Cl + (size_t)(row + 8) * M + col) = __halves2half2(lx, ly);
            } else {
                *(float2*)(C + (size_t)row * M + col)       = o0;
                *(float2*)(C + (size_t)(row + 8) * M + col) = o1;
            }
        }
    }
}

// ---------------- prep: cb split + csq + commit=0 --------------------------
__global__ void prep_kernel(const float* __restrict__ cb) {
    const int b = blockIdx.x;
    const int t = threadIdx.x;
    if (b < 512) {
        int idx = b * 256 + t;
        __half h, l;
        split_h(cb[idx], h, l);
        g_cbH[idx] = h;
        g_cbL[idx] = l;
    } else {
        int k = (b - 512) * 256 + t;
        if (b == 512 && t == 0) g_commit = 0.0;
        const float* row = cb + (size_t)k * CBD;
        float s = 0.f;
#pragma unroll 8
        for (int c = 0; c < CBD; c += 4) {
            float4 v = *(const float4*)(row + c);
            s += v.x*v.x + v.y*v.y + v.z*v.z + v.w*v.w;
        }
        g_csq[k] = s;
    }
}

// ---------------- split x into fp16 hi/lo planes ---------------------------
__global__ void split_x_kernel(const float* __restrict__ x) {
    size_t i = ((size_t)blockIdx.x * 256 + threadIdx.x) * 4;
    float4 v = *(const float4*)(x + i);
    __half h0, l0, h1, l1, h2, l2, h3, l3;
    split_h(v.x, h0, l0); split_h(v.y, h1, l1);
    split_h(v.z, h2, l2); split_h(v.w, h3, l3);
    *(__half2*)(g_xh + i)     = __halves2half2(h0, h1);
    *(__half2*)(g_xh + i + 2) = __halves2half2(h2, h3);
    *(__half2*)(g_xl + i)     = __halves2half2(l0, l1);
    *(__half2*)(g_xl + i + 2) = __halves2half2(l2, l3);
}

// ---------------- transpose + split: W[K,M] -> half planes [M,K] -----------
__global__ void transpose_split(const float* __restrict__ W,
                                __half* __restrict__ WTh, __half* __restrict__ WTl,
                                int K, int M) {
    int idx = blockIdx.x * 256 + threadIdx.x;
    if (idx < K * M) {
        int m = idx / K, k = idx - m * K;
        __half h, l;
        split_h(W[(size_t)k * M + m], h, l);
        WTh[idx] = h;
        WTl[idx] = l;
    }
}

// ---------------- fp32 SGEMM for the tiny decoder-table GEMMs -------------
template<bool RELU, bool HASBIAS>
__global__ void __launch_bounds__(256) sgemm_kernel(
    const float* __restrict__ A, const float* __restrict__ B,
    const float* __restrict__ bias, float* __restrict__ C,
    int N, int K, int M)
{
    __shared__ float As[16][132];
    __shared__ float Bs[16][72];
    const int tid  = threadIdx.x;
    const int tx   = tid & 15;
    const int ty   = tid >> 4;
    const int brow = blockIdx.y << 7;
    const int bcol = blockIdx.x << 6;

    const int ar = tid >> 2;
    const int ac = (tid & 3) << 2;
    const float* a0 = A + (size_t)(brow + ar) * K + ac;
    const float* a1 = A + (size_t)(brow + ar + 64) * K + ac;
    const int br = tid >> 4;
    const int bc = (tid & 15) << 2;
    const float* bptr = B + (size_t)br * M + bcol + bc;

    float acc[8][4];
#pragma unroll
    for (int i = 0; i < 8; i++)
#pragma unroll
        for (int j = 0; j < 4; j++) acc[i][j] = 0.f;

    for (int k0 = 0; k0 < K; k0 += 16) {
        float4 av0 = *(const float4*)(a0 + k0);
        float4 av1 = *(const float4*)(a1 + k0);
        float4 bv  = *(const float4*)(bptr + (size_t)k0 * M);
        As[ac + 0][ar] = av0.x;  As[ac + 1][ar] = av0.y;
        As[ac + 2][ar] = av0.z;  As[ac + 3][ar] = av0.w;
        As[ac + 0][ar + 64] = av1.x;  As[ac + 1][ar + 64] = av1.y;
        As[ac + 2][ar + 64] = av1.z;  As[ac + 3][ar + 64] = av1.w;
        *(float4*)&Bs[br][bc] = bv;
        __syncthreads();
#pragma unroll
        for (int kk = 0; kk < 16; kk++) {
            float4 a4l = *(const float4*)&As[kk][ty << 3];
            float4 a4h = *(const float4*)&As[kk][(ty << 3) + 4];
            float4 b4  = *(const float4*)&Bs[kk][tx << 2];
            float arr[8] = {a4l.x, a4l.y, a4l.z, a4l.w, a4h.x, a4h.y, a4h.z, a4h.w};
            float brr[4] = {b4.x, b4.y, b4.z, b4.w};
#pragma unroll
            for (int i = 0; i < 8; i++)
#pragma unroll
                for (int j = 0; j < 4; j++)
                    acc[i][j] = fmaf(arr[i], brr[j], acc[i][j]);
        }
        __syncthreads();
    }

    float4 bb = make_float4(0.f, 0.f, 0.f, 0.f);
    if (HASBIAS) bb = *(const float4*)(bias + bcol + (tx << 2));
#pragma unroll
    for (int i = 0; i < 8; i++) {
        float4 o;
        o.x = acc[i][0] + bb.x;
        o.y = acc[i][1] + bb.y;
        o.z = acc[i][2] + bb.z;
        o.w = acc[i][3] + bb.w;
        if (RELU) {
            o.x = fmaxf(o.x, 0.f); o.y = fmaxf(o.y, 0.f);
            o.z = fmaxf(o.z, 0.f); o.w = fmaxf(o.w, 0.f);
        }
        *(float4*)(C + (size_t)(brow + (ty << 3) + i) * M + bcol + (tx << 2)) = o;
    }
}

// ---- VQ: reduce 4 partials + commit partial + recon gather ---------------
__global__ void __launch_bounds__(256) vq_recon_kernel(
    const float2* __restrict__ part,
    const __half* __restrict__ zH, const __half* __restrict__ zL,
    const float* __restrict__ R, float* __restrict__ out_idx,
    float* __restrict__ out_recon)
{
    __shared__ float s_part[8];
    const int tid = threadIdx.x;
    const int token = (blockIdx.x << 6) + (tid >> 2);
    const int lpart = tid & 3;

    float2 e = part[(size_t)token * 4 + lpart];
    float best = e.x;
    int   bidx = (int)e.y;
#pragma unroll
    for (int off = 1; off < 4; off <<= 1) {
        float ob = __shfl_xor_sync(0xffffffffu, best, off);
        int   oi = __shfl_xor_sync(0xffffffffu, bidx, off);
        if (ob < best || (ob == best && oi < bidx)) { best = ob; bidx = oi; }
    }

    // ||z||^2 from half planes (z = zH + zL); 64 coords per lane
    const __half2* zh2 = (const __half2*)(zH + (size_t)token * CBD + (lpart << 6));
    const __half2* zl2 = (const __half2*)(zL + (size_t)token * CBD + (lpart << 6));
    float s = 0.f;
#pragma unroll
    for (int i = 0; i < 32; i++) {
        float2 a = __half22float2(zh2[i]);
        float2 b = __half22float2(zl2[i]);
        float vx = a.x + b.x, vy = a.y + b.y;
        s += vx * vx + vy * vy;
    }
    s += __shfl_xor_sync(0xffffffffu, s, 1);
    s += __shfl_xor_sync(0xffffffffu, s, 2);

    float cv = (lpart == 0) ? (s + best) : 0.f;
    if (lpart == 0) out_idx[token] = (float)bidx;

    const float4* src = (const float4*)(R + (size_t)bidx * D_IN + lpart * 192);
    float4*       dst = (float4*)(out_recon + (size_t)token * D_IN + lpart * 192);
#pragma unroll 4
    for (int i = 0; i < 48; i++) dst[i] = src[i];

#pragma unroll
    for (int off = 16; off; off >>= 1) cv += __shfl_xor_sync(0xffffffffu, cv, off);
    if ((tid & 31) == 0) s_part[tid >> 5] = cv;
    __syncthreads();
    if (tid == 0) {
        float t = 0.f;
#pragma unroll
        for (int w = 0; w < 8; w++) t += s_part[w];
        atomicAdd(&g_commit, (double)t);
    }
}

__global__ void finalize_kernel(float* __restrict__ out_loss) {
    *out_loss = (float)(g_commit * (1.0 / ((double)NTOK * CBD)));
}

// ---------------- launch ---------------------------------------------------
extern "C" void kernel_launch(void* const* d_in, const int* in_sizes, int n_in,
                              void* d_out, int out_size) {
    const float* x  = (const float*)d_in[0];
    const float* W1 = (const float*)d_in[1];
    const float* b1 = (const float*)d_in[2];
    const float* W2 = (const float*)d_in[3];
    const float* b2 = (const float*)d_in[4];
    const float* cb = (const float*)d_in[5];
    const float* W3 = (const float*)d_in[6];
    const float* b3 = (const float*)d_in[7];
    const float* W4 = (const float*)d_in[8];
    const float* b4 = (const float*)d_in[9];

    float* out       = (float*)d_out;
    float* out_recon = out;
    float* out_idx   = out + (size_t)NTOK * D_IN;
    float* out_loss  = out_idx + NTOK;

    __half *pxh, *pxl, *phH, *phL, *pzH, *pzL;
    __half *pW1TH, *pW1TL, *pW2TH, *pW2TL, *pcbH, *pcbL;
    float *pT1, *pR;
    float2* ppart;
    cudaGetSymbolAddress((void**)&pxh,   g_xh);
    cudaGetSymbolAddress((void**)&pxl,   g_xl);
    cudaGetSymbolAddress((void**)&phH,   g_hH);
    cudaGetSymbolAddress((void**)&phL,   g_hL);
    cudaGetSymbolAddress((void**)&pzH,   g_zH);
    cudaGetSymbolAddress((void**)&pzL,   g_zL);
    cudaGetSymbolAddress((void**)&ppart, g_part);
    cudaGetSymbolAddress((void**)&pT1,   g_T1);
    cudaGetSymbolAddress((void**)&pR,    g_R);
    cudaGetSymbolAddress((void**)&pW1TH, g_W1TH);
    cudaGetSymbolAddress((void**)&pW1TL, g_W1TL);
    cudaGetSymbolAddress((void**)&pW2TH, g_W2TH);
    cudaGetSymbolAddress((void**)&pW2TL, g_W2TL);
    cudaGetSymbolAddress((void**)&pcbH,  g_cbH);
    cudaGetSymbolAddress((void**)&pcbL,  g_cbL);

    static bool attr_done = false;
    if (!attr_done) {
        cudaFuncSetAttribute(hmma_gemm<true,  true,  true,  false>,
                             cudaFuncAttributeMaxDynamicSharedMemorySize, HSMEM);
        cudaFuncSetAttribute(hmma_gemm<false, true,  true,  false>,
                             cudaFuncAttributeMaxDynamicSharedMemorySize, HSMEM);
        cudaFuncSetAttribute(hmma_gemm<false, false, false, true >,
                             cudaFuncAttributeMaxDynamicSharedMemorySize, HSMEM);
        attr_done = true;
    }

    // [0] prep: cb split + csq + commit=0
    prep_kernel<<<514, 256>>>(cb);
    // [1] split x into fp16 planes
    split_x_kernel<<<(NTOK * D_IN / 4) / 256, 256>>>(x);
    // [2] W1 transpose+split
    transpose_split<<<(HID * D_IN + 255) / 256, 256>>>(W1, pW1TH, pW1TL, D_IN, HID);
    // [3] h = relu(x @ W1 + b1), split output   (ncu-captured slot)
    hmma_gemm<true,  true,  true,  false><<<dim3(HID / 128, NTOK / 128), 128, HSMEM>>>(
        pxh, pxl, pW1TH, pW1TL, b1, nullptr, phH, phL, nullptr, D_IN, HID);
    // [4] W2 transpose+split
    transpose_split<<<(CBD * HID + 255) / 256, 256>>>(W2, pW2TH, pW2TL, HID, CBD);
    // [5][6] decoder table (tiny, fp32)
    sgemm_kernel<true , true ><<<dim3(HID  / 64, 512 / 128), 256>>>(cb,  W3, b3, pT1, 512, CBD, HID);
    sgemm_kernel<false, true ><<<dim3(D_IN / 64, 512 / 128), 256>>>(pT1, W4, b4, pR,  512, HID, D_IN);
    // [7] z = h @ W2 + b2, split output
    hmma_gemm<false, true,  true,  false><<<dim3(CBD / 128, NTOK / 128), 128, HSMEM>>>(
        phH, phL, pW2TH, pW2TL, b2, nullptr, pzH, pzL, nullptr, HID, CBD);
    // [8] dots + fused argmin -> partials
    hmma_gemm<false, false, false, true ><<<dim3(CBK / 128, NTOK / 128), 128, HSMEM>>>(
        pzH, pzL, pcbH, pcbL, nullptr, nullptr, nullptr, nullptr, ppart, CBD, CBK);
    // [9] reduce partials + commit + recon gather
    vq_recon_kernel<<<NTOK / 64, 256>>>(ppart, pzH, pzL, pR, out_idx, out_recon);
    // [10] loss
    finalize_kernel<<<1, 1>>>(out_loss);
}